// round 14
// baseline (speedup 1.0000x reference)
#include <cuda_runtime.h>
#include <cuda_bf16.h>

#define B    4
#define C    256
#define CQK  16
#define MT   64
#define NT   128
#define N    4096
#define NTILES (N / NT)
#define LOG2E 1.4426950408889634f
#define SBIAS 20.0f     // P = 2^(s*log2e - SBIAS); cancels in o/L

typedef unsigned long long u64;
typedef unsigned int u32;
typedef unsigned short u16;
typedef unsigned char u8;

// Scratch: q,k bf16 [B][N][16] (q pre-scaled by log2e); v e4m3 [B][C][N]
// g_w: packed weights bf16 [288][256]: rows 0-15 Wq*log2e, 16-31 Wk, 32-287 Wv
__device__ __nv_bfloat16 g_q[(size_t)B * N * CQK];
__device__ __nv_bfloat16 g_k[(size_t)B * N * CQK];
__device__ u8            g_v[(size_t)B * C * N];
__device__ __nv_bfloat16 g_w[288 * 256];

// ---- bf16 / f16 / fp8 helpers --------------------------------------------------
__device__ __forceinline__ u32 bf2(float lo, float hi) {
    u32 r; asm("cvt.rn.bf16x2.f32 %0,%1,%2;" : "=r"(r) : "f"(hi), "f"(lo)); return r;
}
__device__ __forceinline__ u32 hpack(float lo, float hi) {
    u32 r; asm("cvt.rn.f16x2.f32 %0,%1,%2;" : "=r"(r) : "f"(hi), "f"(lo)); return r;
}
__device__ __forceinline__ u32 ex2h2(u32 s) {
    u32 d; asm("ex2.approx.f16x2 %0,%1;" : "=r"(d) : "r"(s)); return d;
}
__device__ __forceinline__ u32 hadd2(u32 a, u32 b) {
    u32 d; asm("add.rn.f16x2 %0,%1,%2;" : "=r"(d) : "r"(a), "r"(b)); return d;
}
__device__ __forceinline__ u16 e4m3h2(u32 h) {
    u16 d; asm("cvt.rn.satfinite.e4m3x2.f16x2 %0,%1;" : "=h"(d) : "r"(h)); return d;
}
__device__ __forceinline__ u16 e4m3f2(float lo, float hi) {
    u16 d; asm("cvt.rn.satfinite.e4m3x2.f32 %0,%1,%2;" : "=h"(d) : "f"(hi), "f"(lo)); return d;
}
__device__ __forceinline__ float h2sum(u32 h) {
    float a, b;
    asm("{.reg .f16 x,y; mov.b32 {x,y},%2; cvt.f32.f16 %0,x; cvt.f32.f16 %1,y;}"
        : "=f"(a), "=f"(b) : "r"(h));
    return a + b;
}

// ---- tensor-core helpers (u32 shared addresses) ---------------------------------
__device__ __forceinline__ u32 smem_u32(const void* p) {
    u32 a;
    asm("{ .reg .u64 t; cvta.to.shared.u64 t, %1; cvt.u32.u64 %0, t; }" : "=r"(a) : "l"(p));
    return a;
}
__device__ __forceinline__ void ldsm4(u32* r, u32 a) {
    asm volatile("ldmatrix.sync.aligned.m8n8.x4.shared.b16 {%0,%1,%2,%3},[%4];"
                 : "=r"(r[0]), "=r"(r[1]), "=r"(r[2]), "=r"(r[3]) : "r"(a));
}
__device__ __forceinline__ void ldsm4t(u32* r, u32 a) {
    asm volatile("ldmatrix.sync.aligned.m8n8.x4.trans.shared.b16 {%0,%1,%2,%3},[%4];"
                 : "=r"(r[0]), "=r"(r[1]), "=r"(r[2]), "=r"(r[3]) : "r"(a));
}
__device__ __forceinline__ void mma_bf16(float* d, const u32* a, const u32* b) {
    asm volatile("mma.sync.aligned.m16n8k16.row.col.f32.bf16.bf16.f32 "
                 "{%0,%1,%2,%3},{%4,%5,%6,%7},{%8,%9},{%0,%1,%2,%3};"
                 : "+f"(d[0]), "+f"(d[1]), "+f"(d[2]), "+f"(d[3])
                 : "r"(a[0]), "r"(a[1]), "r"(a[2]), "r"(a[3]), "r"(b[0]), "r"(b[1]));
}
__device__ __forceinline__ void mma_e4m3(float* d, const u32* a, const u32* b) {
    asm volatile("mma.sync.aligned.m16n8k32.row.col.f32.e4m3.e4m3.f32 "
                 "{%0,%1,%2,%3},{%4,%5,%6,%7},{%8,%9},{%0,%1,%2,%3};"
                 : "+f"(d[0]), "+f"(d[1]), "+f"(d[2]), "+f"(d[3])
                 : "r"(a[0]), "r"(a[1]), "r"(a[2]), "r"(a[3]), "r"(b[0]), "r"(b[1]));
}
#define CP_COMMIT() asm volatile("cp.async.commit_group;" ::: "memory")
#define CP_WAIT1()  asm volatile("cp.async.wait_group 1;" ::: "memory")

// ---------------------------------------------------------------------------
// Weight pack: g_w[o][c] bf16; q rows pre-scaled by log2e. grid 288 x 256 thr.
// ---------------------------------------------------------------------------
__global__ void wcvt_kernel(const float* __restrict__ Wq,
                            const float* __restrict__ Wk,
                            const float* __restrict__ Wv)
{
    int idx = blockIdx.x * 256 + threadIdx.x;
    int o = idx >> 8, c = idx & 255;
    float v;
    if (o < 16)      v = Wq[o * C + c] * LOG2E;
    else if (o < 32) v = Wk[(o - 16) * C + c];
    else             v = Wv[(o - 32) * C + c];
    g_w[idx] = __float2bfloat16_rn(v);
}

// ---------------------------------------------------------------------------
// Tensor-core projection (unchanged from R12).
// ---------------------------------------------------------------------------
#define WS 80
#define XS 144
#define PM_W 0
#define PM_X (3*288*WS)
#define PM_TOTAL (PM_X + 3*32*XS)

__global__ __launch_bounds__(256) void proj_mma_kernel(
    const float* __restrict__ x,
    const float* __restrict__ bq, const float* __restrict__ bk,
    const float* __restrict__ bv)
{
    extern __shared__ char smc[];
    const u32 sb = smem_u32(smc);
    const int t = threadIdx.x, lane = t & 31, w = t >> 5;
    const int b = blockIdx.y, n0 = blockIdx.x * 64;
    const int lj = lane >> 3, li = lane & 7, r = lane >> 2, cq = lane & 3;
    const int ldA  = (lj & 1) * 8 + li;
    const int ldAc = (lj >> 1) * 16;

    const float* xb = x + (size_t)b * C * N + n0;

    auto load_w = [&](int kc, int buf) {
        u32 dst = sb + PM_W + buf * (288 * WS);
        const char* src = (const char*)g_w + kc * 64;
        #pragma unroll
        for (int i = 0; i < 5; i++) {
            int idx = t + i * 256;
            if (idx < 1152) {
                int o = idx >> 2, col = idx & 3;
                asm volatile("cp.async.cg.shared.global [%0],[%1],16;"
                             :: "r"(dst + o * WS + col * 16),
                                "l"(src + o * 512 + col * 16) : "memory");
            }
        }
    };
    auto load_x = [&](int kc, int buf) {
        char* dst = smc + PM_X + buf * (32 * XS);
        #pragma unroll
        for (int i = 0; i < 2; i++) {
            int idx = t + i * 256;
            int c = idx >> 4, nq = idx & 15;
            float4 v4 = *(const float4*)(xb + (size_t)(kc * 32 + c) * N + nq * 4);
            *(uint2*)(dst + c * XS + nq * 8) =
                make_uint2(bf2(v4.x, v4.y), bf2(v4.z, v4.w));
        }
    };

    float d[2][8][4], dq[8][4];
    {
        float b0 = bv[w * 32 + r],      b1 = bv[w * 32 + r + 8];
        float b2 = bv[w * 32 + 16 + r], b3 = bv[w * 32 + 16 + r + 8];
        float c0 = 0.f, c1 = 0.f;
        if (w == 0) { c0 = bq[r] * LOG2E; c1 = bq[r + 8] * LOG2E; }
        if (w == 1) { c0 = bk[r];         c1 = bk[r + 8]; }
        #pragma unroll
        for (int jn = 0; jn < 8; jn++) {
            d[0][jn][0] = b0; d[0][jn][1] = b0; d[0][jn][2] = b1; d[0][jn][3] = b1;
            d[1][jn][0] = b2; d[1][jn][1] = b2; d[1][jn][2] = b3; d[1][jn][3] = b3;
            dq[jn][0] = c0; dq[jn][1] = c0; dq[jn][2] = c1; dq[jn][3] = c1;
        }
    }

    load_w(0, 0); load_x(0, 0); CP_COMMIT();
    load_w(1, 1); load_x(1, 1); CP_COMMIT();

    const int obase = 32 + w * 32;

    #pragma unroll 1
    for (int kc = 0; kc < 8; kc++) {
        const int cur = kc % 3;
        CP_WAIT1();
        __syncthreads();
        if (kc + 2 < 8) { load_w(kc + 2, (kc + 2) % 3); load_x(kc + 2, (kc + 2) % 3); }
        CP_COMMIT();

        const u32 wbase = sb + PM_W + cur * (288 * WS);
        const u32 xbase = sb + PM_X + cur * (32 * XS);
        #pragma unroll
        for (int ks = 0; ks < 2; ks++) {
            u32 a0[4], a1[4], aq[4];
            ldsm4(a0, wbase + (u32)((obase      + ldA) * WS + ks * 32 + ldAc));
            ldsm4(a1, wbase + (u32)((obase + 16 + ldA) * WS + ks * 32 + ldAc));
            if (w < 2)
                ldsm4(aq, wbase + (u32)((w * 16 + ldA) * WS + ks * 32 + ldAc));
            #pragma unroll
            for (int nf = 0; nf < 4; nf++) {
                u32 bf[4];
                ldsm4t(bf, xbase + (u32)((ks * 16 + ldA) * XS + nf * 32 + ldAc));
                mma_bf16(d[0][2 * nf    ], a0, bf);
                mma_bf16(d[0][2 * nf + 1], a0, bf + 2);
                mma_bf16(d[1][2 * nf    ], a1, bf);
                mma_bf16(d[1][2 * nf + 1], a1, bf + 2);
                if (w < 2) {
                    mma_bf16(dq[2 * nf    ], aq, bf);
                    mma_bf16(dq[2 * nf + 1], aq, bf + 2);
                }
            }
        }
    }

    #pragma unroll
    for (int mi = 0; mi < 2; mi++) {
        int o = w * 32 + mi * 16 + r;
        u8* vrow0 = g_v + ((size_t)b * C + o) * N + n0;
        u8* vrow1 = vrow0 + (size_t)8 * N;
        #pragma unroll
        for (int jn = 0; jn < 8; jn++) {
            int nb = jn * 8 + 2 * cq;
            *(u16*)(vrow0 + nb) = e4m3f2(d[mi][jn][0], d[mi][jn][1]);
            *(u16*)(vrow1 + nb) = e4m3f2(d[mi][jn][2], d[mi][jn][3]);
        }
    }
    if (w < 2) {
        __nv_bfloat16* gqk = (w == 0 ? g_q : g_k) + (size_t)b * N * CQK;
        #pragma unroll
        for (int jn = 0; jn < 8; jn++) {
            int n = n0 + jn * 8 + 2 * cq;
            gqk[(size_t)n * CQK + r]           = __float2bfloat16_rn(dq[jn][0]);
            gqk[(size_t)(n + 1) * CQK + r]     = __float2bfloat16_rn(dq[jn][1]);
            gqk[(size_t)n * CQK + r + 8]       = __float2bfloat16_rn(dq[jn][2]);
            gqk[(size_t)(n + 1) * CQK + r + 8] = __float2bfloat16_rn(dq[jn][3]);
        }
    }
}

// ---------------------------------------------------------------------------
// Flash attention, 2 CTAs/SM, fp8 PV, NT=128, software-pipelined fragments.
// ---------------------------------------------------------------------------
#define QKS 48
#define PS  144
#define VS  144
#define SM_L   0
#define SM_K   512
#define SM_Q   (SM_K + 64*QKS)
#define SM_P   (SM_Q + 3*128*QKS)
#define SM_V   (SM_P + 2*64*PS)
#define SM_TOTAL (SM_V + 2*256*VS)

#define QBUF (128*QKS)
#define PBUF (64*PS)
#define VBUF (256*VS)

__global__ __launch_bounds__(256, 2) void attn_kernel(
    const float* __restrict__ x,
    const float* __restrict__ gamma,
    float* __restrict__ out)
{
    extern __shared__ char smc[];
    float* L_s = (float*)(smc + SM_L);
    const u32 sbase = smem_u32(smc);

    const int t    = threadIdx.x;
    const int bb   = blockIdx.y;
    const int m0   = blockIdx.x * MT;
    const int lane = t & 31;
    const int w    = t >> 5;

    const int mt = w & 3;
    const int nq = w >> 2;
    const int ct0 = w * 32;

    const int lj = lane >> 3;
    const int li = lane & 7;
    const int r  = lane >> 2;
    const int cq = lane & 3;

    const int ldA = (lj & 1) * 8 + li;
    const int ldAc = (lj >> 1) * 16;
    const int ldB = (lj >> 1) * 8 + li;
    const int ldBc = (lj & 1) * 16;

    const u32 qfragA = sbase + SM_Q + (u32)((nq * 64 +      ldB) * QKS + ldBc);
    const u32 qfragB = sbase + SM_Q + (u32)((nq * 64 + 16 + ldB) * QKS + ldBc);
    u32 vfrag[2], pfrag[4];
    #pragma unroll
    for (int ct = 0; ct < 2; ct++)
        vfrag[ct] = sbase + SM_V + (u32)((ct0 + ct * 16 + ldA) * VS + ldAc);
    #pragma unroll
    for (int mp = 0; mp < 4; mp++)
        pfrag[mp] = sbase + SM_P + (u32)((mp * 16 + ldB) * PS + ldBc);
    char* const psto0 = smc + SM_P + (mt * 16 + r)     * PS + nq * 64 + 2 * cq;
    char* const psto1 = smc + SM_P + (mt * 16 + r + 8) * PS + nq * 64 + 2 * cq;

    if (t < MT) L_s[t] = 0.f;
    if (t < 128) {
        int m = t >> 1, half = t & 1;
        *(uint4*)(smc + SM_K + m * QKS + half * 16) =
            *(const uint4*)(g_k + ((size_t)bb * N + m0 + m) * CQK + half * 8);
    }

    const __nv_bfloat16* gq_p =
        g_q + ((size_t)bb * N + (t >> 1)) * CQK + (size_t)(t & 1) * 8;
    const u8* gv_p = g_v + ((size_t)bb * C + (t >> 3)) * N + (size_t)(t & 7) * 16;
    char* const qsto = smc + SM_Q + (t >> 1) * QKS + (t & 1) * 16;
    char* const vsto = smc + SM_V + (t >> 3) * VS + (t & 7) * 16;

    auto load_q = [&](u32 qWo) {
        *(uint4*)(qsto + qWo) = *(const uint4*)gq_p;
        gq_p += NT * CQK;
    };
    auto load_v = [&](u32 vWo) {
        char* vd = vsto + vWo;
        #pragma unroll
        for (int i8 = 0; i8 < 8; i8++)
            *(uint4*)(vd + i8 * (32 * VS)) =
                *(const uint4*)(gv_p + (size_t)i8 * 32 * N);
        gv_p += NT;
    };

    load_q(0);
    load_v(0);
    load_q(QBUF);
    __syncthreads();

    u32 aK[4];
    ldsm4(aK, sbase + SM_K + (u32)((mt * 16 + ldA) * QKS + ldAc));

    float Lacc0 = 0.f, Lacc8 = 0.f;

    // S: all 4 Q-fragment ldsm issued up front, then 8 HMMA, then exp/STS.
    auto s_compute = [&](u32 qRo, u32 pWo) {
        u32 b0[2][4], b1[2][4];
        ldsm4(b0[0], qfragA + qRo);
        ldsm4(b1[0], qfragB + qRo);
        ldsm4(b0[1], qfragA + qRo + 32 * QKS);
        ldsm4(b1[1], qfragB + qRo + 32 * QKS);

        u32 Lt0 = 0, Lt8 = 0;
        char* pb0 = psto0 + pWo;
        char* pb1 = psto1 + pWo;
        #pragma unroll
        for (int nh2 = 0; nh2 < 2; nh2++) {
            float d[4][4];
            #pragma unroll
            for (int j = 0; j < 4; j++)
                #pragma unroll
                for (int e = 0; e < 4; e++) d[j][e] = -SBIAS;
            mma_bf16(d[0], aK, b0[nh2]);
            mma_bf16(d[1], aK, b0[nh2] + 2);
            mma_bf16(d[2], aK, b1[nh2]);
            mma_bf16(d[3], aK, b1[nh2] + 2);

            #pragma unroll
            for (int nt = 0; nt < 4; nt++) {
                u32 e0 = ex2h2(hpack(d[nt][0], d[nt][1]));
                u32 e1 = ex2h2(hpack(d[nt][2], d[nt][3]));
                Lt0 = hadd2(Lt0, e0);
                Lt8 = hadd2(Lt8, e1);
                *(u16*)(pb0 + nh2 * 32 + nt * 8) = e4m3h2(e0);
                *(u16*)(pb1 + nh2 * 32 + nt * 8) = e4m3h2(e1);
            }
        }
        Lacc0 += h2sum(Lt0);
        Lacc8 += h2sum(Lt8);
    };

    float d_acc[2][8][4];
    #pragma unroll
    for (int ct = 0; ct < 2; ct++)
        #pragma unroll
        for (int mp = 0; mp < 8; mp++)
            #pragma unroll
            for (int e = 0; e < 4; e++) d_acc[ct][mp][e] = 0.f;

    s_compute(0, 0);
    __syncthreads();

    u32 qRo = QBUF, qIo = 0, qWo = 2 * QBUF;
    u32 vRo = 0, vWo = VBUF;
    u32 pWo = PBUF, pRo = 0;

    for (int tile = 0; tile < NTILES; ++tile) {
        if (tile + 2 < NTILES) load_q(qWo);
        if (tile + 1 < NTILES) { load_v(vWo); s_compute(qRo, pWo); }

        // ---- PV: software-pipelined fragment loads ----
        {
            u32 av[2][4];      // V fragments for current ks
            u32 bf[2][4];      // P fragments, double-buffered by step parity
            ldsm4(av[0], vfrag[0] + vRo);
            ldsm4(av[1], vfrag[1] + vRo);
            ldsm4(bf[0], pfrag[0] + pRo);
            #pragma unroll
            for (int ks = 0; ks < 4; ks++) {
                #pragma unroll
                for (int mp = 0; mp < 4; mp++) {
                    const int step = ks * 4 + mp;
                    const int pc = step & 1;
                    // prefetch next P fragment before consuming current one
                    if (mp < 3)
                        ldsm4(bf[pc ^ 1], pfrag[mp + 1] + pRo + ks * 32);
                    else if (ks < 3)
                        ldsm4(bf[pc ^ 1], pfrag[0] + pRo + (ks + 1) * 32);
                    mma_e4m3(d_acc[0][2 * mp    ], av[0], bf[pc]);
                    mma_e4m3(d_acc[0][2 * mp + 1], av[0], bf[pc] + 2);
                    mma_e4m3(d_acc[1][2 * mp    ], av[1], bf[pc]);
                    mma_e4m3(d_acc[1][2 * mp + 1], av[1], bf[pc] + 2);
                    // refresh V fragments early in each ks (after mp=0 mma batch)
                    if (mp == 0 && ks < 3) {
                        ldsm4(av[0], vfrag[0] + vRo + (ks + 1) * 32);
                        ldsm4(av[1], vfrag[1] + vRo + (ks + 1) * 32);
                    }
                }
            }
        }
        __syncthreads();

        u32 tq = qRo; qRo = qWo; qWo = qIo; qIo = tq;
        vRo ^= VBUF; vWo ^= VBUF;
        pWo ^= PBUF; pRo ^= PBUF;
    }

    Lacc0 += __shfl_xor_sync(0xffffffffu, Lacc0, 1);
    Lacc0 += __shfl_xor_sync(0xffffffffu, Lacc0, 2);
    Lacc8 += __shfl_xor_sync(0xffffffffu, Lacc8, 1);
    Lacc8 += __shfl_xor_sync(0xffffffffu, Lacc8, 2);
    if (cq == 0) {
        atomicAdd(&L_s[mt * 16 + r],     Lacc0);
        atomicAdd(&L_s[mt * 16 + r + 8], Lacc8);
    }
    __syncthreads();
    if (t < MT) L_s[t] = 1.0f / fmaxf(L_s[t], 1e-30f);
    __syncthreads();

    const float g = gamma[0];
    #pragma unroll
    for (int ct = 0; ct < 2; ct++) {
        #pragma unroll
        for (int half = 0; half < 2; half++) {
            int c = ct0 + ct * 16 + r + half * 8;
            #pragma unroll
            for (int mp = 0; mp < 8; mp++) {
                int mloc = mp * 8 + cq * 2;
                float iL0 = L_s[mloc], iL1 = L_s[mloc + 1];
                size_t idx = ((size_t)bb * C + c) * N + m0 + mloc;
                float2 xv = *(const float2*)&x[idx];
                float2 ov;
                ov.x = xv.x + g * d_acc[ct][mp][half * 2    ] * iL0;
                ov.y = xv.y + g * d_acc[ct][mp][half * 2 + 1] * iL1;
                *(float2*)&out[idx] = ov;
            }
        }
    }
}

// ---------------------------------------------------------------------------
extern "C" void kernel_launch(void* const* d_in, const int* in_sizes, int n_in,
                              void* d_out, int out_size)
{
    const float* x     = (const float*)d_in[0];
    const float* Wq    = (const float*)d_in[1];
    const float* bq    = (const float*)d_in[2];
    const float* Wk    = (const float*)d_in[3];
    const float* bk    = (const float*)d_in[4];
    const float* Wv    = (const float*)d_in[5];
    const float* bv    = (const float*)d_in[6];
    const float* gamma = (const float*)d_in[7];
    float* out = (float*)d_out;

    wcvt_kernel<<<288, 256>>>(Wq, Wk, Wv);

    cudaFuncSetAttribute(proj_mma_kernel,
                         cudaFuncAttributeMaxDynamicSharedMemorySize, PM_TOTAL);
    proj_mma_kernel<<<dim3(N / 64, B), 256, PM_TOTAL>>>(x, bq, bk, bv);

    cudaFuncSetAttribute(attn_kernel,
                         cudaFuncAttributeMaxDynamicSharedMemorySize, SM_TOTAL);
    attn_kernel<<<dim3(N / MT, B), 256, SM_TOTAL>>>(x, gamma, out);
}

// round 16
// speedup vs baseline: 1.0840x; 1.0840x over previous
#include <cuda_runtime.h>
#include <cuda_bf16.h>

#define B    4
#define C    256
#define CQK  16
#define MT   64
#define NT   128
#define N    4096
#define NTILES (N / NT)
#define LOG2E 1.4426950408889634f
#define SBIAS 20.0f     // P = 2^(s*log2e - SBIAS); cancels in o/L

typedef unsigned long long u64;
typedef unsigned int u32;
typedef unsigned short u16;
typedef unsigned char u8;

// Scratch: q,k bf16 [B][N][16] (q pre-scaled by log2e); v e4m3 [B][C][N]
// g_w: packed weights bf16 [288][256]: rows 0-15 Wq*log2e, 16-31 Wk, 32-287 Wv
__device__ __nv_bfloat16 g_q[(size_t)B * N * CQK];
__device__ __nv_bfloat16 g_k[(size_t)B * N * CQK];
__device__ u8            g_v[(size_t)B * C * N];
__device__ __nv_bfloat16 g_w[288 * 256];

// ---- bf16 / f16 / fp8 helpers --------------------------------------------------
__device__ __forceinline__ u32 bf2(float lo, float hi) {
    u32 r; asm("cvt.rn.bf16x2.f32 %0,%1,%2;" : "=r"(r) : "f"(hi), "f"(lo)); return r;
}
__device__ __forceinline__ u32 hpack(float lo, float hi) {
    u32 r; asm("cvt.rn.f16x2.f32 %0,%1,%2;" : "=r"(r) : "f"(hi), "f"(lo)); return r;
}
__device__ __forceinline__ u32 ex2h2(u32 s) {
    u32 d; asm("ex2.approx.f16x2 %0,%1;" : "=r"(d) : "r"(s)); return d;
}
__device__ __forceinline__ u32 hadd2(u32 a, u32 b) {
    u32 d; asm("add.rn.f16x2 %0,%1,%2;" : "=r"(d) : "r"(a), "r"(b)); return d;
}
__device__ __forceinline__ u16 e4m3h2(u32 h) {
    u16 d; asm("cvt.rn.satfinite.e4m3x2.f16x2 %0,%1;" : "=h"(d) : "r"(h)); return d;
}
__device__ __forceinline__ u16 e4m3f2(float lo, float hi) {
    u16 d; asm("cvt.rn.satfinite.e4m3x2.f32 %0,%1,%2;" : "=h"(d) : "f"(hi), "f"(lo)); return d;
}
__device__ __forceinline__ float h2sum(u32 h) {
    float a, b;
    asm("{.reg .f16 x,y; mov.b32 {x,y},%2; cvt.f32.f16 %0,x; cvt.f32.f16 %1,y;}"
        : "=f"(a), "=f"(b) : "r"(h));
    return a + b;
}

// ---- tensor-core helpers (u32 shared addresses) ---------------------------------
__device__ __forceinline__ u32 smem_u32(const void* p) {
    u32 a;
    asm("{ .reg .u64 t; cvta.to.shared.u64 t, %1; cvt.u32.u64 %0, t; }" : "=r"(a) : "l"(p));
    return a;
}
__device__ __forceinline__ void ldsm4(u32* r, u32 a) {
    asm volatile("ldmatrix.sync.aligned.m8n8.x4.shared.b16 {%0,%1,%2,%3},[%4];"
                 : "=r"(r[0]), "=r"(r[1]), "=r"(r[2]), "=r"(r[3]) : "r"(a));
}
__device__ __forceinline__ void ldsm4t(u32* r, u32 a) {
    asm volatile("ldmatrix.sync.aligned.m8n8.x4.trans.shared.b16 {%0,%1,%2,%3},[%4];"
                 : "=r"(r[0]), "=r"(r[1]), "=r"(r[2]), "=r"(r[3]) : "r"(a));
}
__device__ __forceinline__ void mma_bf16(float* d, const u32* a, const u32* b) {
    asm volatile("mma.sync.aligned.m16n8k16.row.col.f32.bf16.bf16.f32 "
                 "{%0,%1,%2,%3},{%4,%5,%6,%7},{%8,%9},{%0,%1,%2,%3};"
                 : "+f"(d[0]), "+f"(d[1]), "+f"(d[2]), "+f"(d[3])
                 : "r"(a[0]), "r"(a[1]), "r"(a[2]), "r"(a[3]), "r"(b[0]), "r"(b[1]));
}
__device__ __forceinline__ void mma_e4m3(float* d, const u32* a, const u32* b) {
    asm volatile("mma.sync.aligned.m16n8k32.row.col.f32.e4m3.e4m3.f32 "
                 "{%0,%1,%2,%3},{%4,%5,%6,%7},{%8,%9},{%0,%1,%2,%3};"
                 : "+f"(d[0]), "+f"(d[1]), "+f"(d[2]), "+f"(d[3])
                 : "r"(a[0]), "r"(a[1]), "r"(a[2]), "r"(a[3]), "r"(b[0]), "r"(b[1]));
}
#define CP_COMMIT() asm volatile("cp.async.commit_group;" ::: "memory")
#define CP_WAIT1()  asm volatile("cp.async.wait_group 1;" ::: "memory")
#define CP_WAIT0()  asm volatile("cp.async.wait_group 0;" ::: "memory")

// ---------------------------------------------------------------------------
// Weight pack: g_w[o][c] bf16; q rows pre-scaled by log2e. grid 288 x 256 thr.
// ---------------------------------------------------------------------------
__global__ void wcvt_kernel(const float* __restrict__ Wq,
                            const float* __restrict__ Wk,
                            const float* __restrict__ Wv)
{
    int idx = blockIdx.x * 256 + threadIdx.x;
    int o = idx >> 8, c = idx & 255;
    float v;
    if (o < 16)      v = Wq[o * C + c] * LOG2E;
    else if (o < 32) v = Wk[(o - 16) * C + c];
    else             v = Wv[(o - 32) * C + c];
    g_w[idx] = __float2bfloat16_rn(v);
}

// ---------------------------------------------------------------------------
// Tensor-core projection (unchanged from R12).
// ---------------------------------------------------------------------------
#define WS 80
#define XS 144
#define PM_W 0
#define PM_X (3*288*WS)
#define PM_TOTAL (PM_X + 3*32*XS)

__global__ __launch_bounds__(256) void proj_mma_kernel(
    const float* __restrict__ x,
    const float* __restrict__ bq, const float* __restrict__ bk,
    const float* __restrict__ bv)
{
    extern __shared__ char smc[];
    const u32 sb = smem_u32(smc);
    const int t = threadIdx.x, lane = t & 31, w = t >> 5;
    const int b = blockIdx.y, n0 = blockIdx.x * 64;
    const int lj = lane >> 3, li = lane & 7, r = lane >> 2, cq = lane & 3;
    const int ldA  = (lj & 1) * 8 + li;
    const int ldAc = (lj >> 1) * 16;

    const float* xb = x + (size_t)b * C * N + n0;

    auto load_w = [&](int kc, int buf) {
        u32 dst = sb + PM_W + buf * (288 * WS);
        const char* src = (const char*)g_w + kc * 64;
        #pragma unroll
        for (int i = 0; i < 5; i++) {
            int idx = t + i * 256;
            if (idx < 1152) {
                int o = idx >> 2, col = idx & 3;
                asm volatile("cp.async.cg.shared.global [%0],[%1],16;"
                             :: "r"(dst + o * WS + col * 16),
                                "l"(src + o * 512 + col * 16) : "memory");
            }
        }
    };
    auto load_x = [&](int kc, int buf) {
        char* dst = smc + PM_X + buf * (32 * XS);
        #pragma unroll
        for (int i = 0; i < 2; i++) {
            int idx = t + i * 256;
            int c = idx >> 4, nq = idx & 15;
            float4 v4 = *(const float4*)(xb + (size_t)(kc * 32 + c) * N + nq * 4);
            *(uint2*)(dst + c * XS + nq * 8) =
                make_uint2(bf2(v4.x, v4.y), bf2(v4.z, v4.w));
        }
    };

    float d[2][8][4], dq[8][4];
    {
        float b0 = bv[w * 32 + r],      b1 = bv[w * 32 + r + 8];
        float b2 = bv[w * 32 + 16 + r], b3 = bv[w * 32 + 16 + r + 8];
        float c0 = 0.f, c1 = 0.f;
        if (w == 0) { c0 = bq[r] * LOG2E; c1 = bq[r + 8] * LOG2E; }
        if (w == 1) { c0 = bk[r];         c1 = bk[r + 8]; }
        #pragma unroll
        for (int jn = 0; jn < 8; jn++) {
            d[0][jn][0] = b0; d[0][jn][1] = b0; d[0][jn][2] = b1; d[0][jn][3] = b1;
            d[1][jn][0] = b2; d[1][jn][1] = b2; d[1][jn][2] = b3; d[1][jn][3] = b3;
            dq[jn][0] = c0; dq[jn][1] = c0; dq[jn][2] = c1; dq[jn][3] = c1;
        }
    }

    load_w(0, 0); load_x(0, 0); CP_COMMIT();
    load_w(1, 1); load_x(1, 1); CP_COMMIT();

    const int obase = 32 + w * 32;

    #pragma unroll 1
    for (int kc = 0; kc < 8; kc++) {
        const int cur = kc % 3;
        CP_WAIT1();
        __syncthreads();
        if (kc + 2 < 8) { load_w(kc + 2, (kc + 2) % 3); load_x(kc + 2, (kc + 2) % 3); }
        CP_COMMIT();

        const u32 wbase = sb + PM_W + cur * (288 * WS);
        const u32 xbase = sb + PM_X + cur * (32 * XS);
        #pragma unroll
        for (int ks = 0; ks < 2; ks++) {
            u32 a0[4], a1[4], aq[4];
            ldsm4(a0, wbase + (u32)((obase      + ldA) * WS + ks * 32 + ldAc));
            ldsm4(a1, wbase + (u32)((obase + 16 + ldA) * WS + ks * 32 + ldAc));
            if (w < 2)
                ldsm4(aq, wbase + (u32)((w * 16 + ldA) * WS + ks * 32 + ldAc));
            #pragma unroll
            for (int nf = 0; nf < 4; nf++) {
                u32 bf[4];
                ldsm4t(bf, xbase + (u32)((ks * 16 + ldA) * XS + nf * 32 + ldAc));
                mma_bf16(d[0][2 * nf    ], a0, bf);
                mma_bf16(d[0][2 * nf + 1], a0, bf + 2);
                mma_bf16(d[1][2 * nf    ], a1, bf);
                mma_bf16(d[1][2 * nf + 1], a1, bf + 2);
                if (w < 2) {
                    mma_bf16(dq[2 * nf    ], aq, bf);
                    mma_bf16(dq[2 * nf + 1], aq, bf + 2);
                }
            }
        }
    }

    #pragma unroll
    for (int mi = 0; mi < 2; mi++) {
        int o = w * 32 + mi * 16 + r;
        u8* vrow0 = g_v + ((size_t)b * C + o) * N + n0;
        u8* vrow1 = vrow0 + (size_t)8 * N;
        #pragma unroll
        for (int jn = 0; jn < 8; jn++) {
            int nb = jn * 8 + 2 * cq;
            *(u16*)(vrow0 + nb) = e4m3f2(d[mi][jn][0], d[mi][jn][1]);
            *(u16*)(vrow1 + nb) = e4m3f2(d[mi][jn][2], d[mi][jn][3]);
        }
    }
    if (w < 2) {
        __nv_bfloat16* gqk = (w == 0 ? g_q : g_k) + (size_t)b * N * CQK;
        #pragma unroll
        for (int jn = 0; jn < 8; jn++) {
            int n = n0 + jn * 8 + 2 * cq;
            gqk[(size_t)n * CQK + r]           = __float2bfloat16_rn(dq[jn][0]);
            gqk[(size_t)(n + 1) * CQK + r]     = __float2bfloat16_rn(dq[jn][1]);
            gqk[(size_t)n * CQK + r + 8]       = __float2bfloat16_rn(dq[jn][2]);
            gqk[(size_t)(n + 1) * CQK + r + 8] = __float2bfloat16_rn(dq[jn][3]);
        }
    }
}

// ---------------------------------------------------------------------------
// Flash attention, 2 CTAs/SM, fp8 PV, NT=128, cp.async tile staging.
// ---------------------------------------------------------------------------
#define QKS 48
#define PS  144
#define VS  144
#define SM_L   0
#define SM_K   512
#define SM_Q   (SM_K + 64*QKS)
#define SM_P   (SM_Q + 3*128*QKS)
#define SM_V   (SM_P + 2*64*PS)
#define SM_TOTAL (SM_V + 2*256*VS)

#define QBUF (128*QKS)
#define PBUF (64*PS)
#define VBUF (256*VS)

__global__ __launch_bounds__(256, 2) void attn_kernel(
    const float* __restrict__ x,
    const float* __restrict__ gamma,
    float* __restrict__ out)
{
    extern __shared__ char smc[];
    float* L_s = (float*)(smc + SM_L);
    const u32 sbase = smem_u32(smc);

    const int t    = threadIdx.x;
    const int bb   = blockIdx.y;
    const int m0   = blockIdx.x * MT;
    const int lane = t & 31;
    const int w    = t >> 5;

    const int mt = w & 3;
    const int nq = w >> 2;
    const int ct0 = w * 32;

    const int lj = lane >> 3;
    const int li = lane & 7;
    const int r  = lane >> 2;
    const int cq = lane & 3;

    const int ldA = (lj & 1) * 8 + li;
    const int ldAc = (lj >> 1) * 16;
    const int ldB = (lj >> 1) * 8 + li;
    const int ldBc = (lj & 1) * 16;

    const u32 qfragA = sbase + SM_Q + (u32)((nq * 64 +      ldB) * QKS + ldBc);
    const u32 qfragB = sbase + SM_Q + (u32)((nq * 64 + 16 + ldB) * QKS + ldBc);
    u32 vfrag[2], pfrag[4];
    #pragma unroll
    for (int ct = 0; ct < 2; ct++)
        vfrag[ct] = sbase + SM_V + (u32)((ct0 + ct * 16 + ldA) * VS + ldAc);
    #pragma unroll
    for (int mp = 0; mp < 4; mp++)
        pfrag[mp] = sbase + SM_P + (u32)((mp * 16 + ldB) * PS + ldBc);
    char* const psto0 = smc + SM_P + (mt * 16 + r)     * PS + nq * 64 + 2 * cq;
    char* const psto1 = smc + SM_P + (mt * 16 + r + 8) * PS + nq * 64 + 2 * cq;

    if (t < MT) L_s[t] = 0.f;
    if (t < 128) {
        int m = t >> 1, half = t & 1;
        *(uint4*)(smc + SM_K + m * QKS + half * 16) =
            *(const uint4*)(g_k + ((size_t)bb * N + m0 + m) * CQK + half * 8);
    }

    // running gmem pointers + fixed smem store slots (cp.async staging)
    // Q tile: 128 rows x 32B -> ALL 256 threads: row = t>>1, half = t&1
    const __nv_bfloat16* gq_p =
        g_q + ((size_t)bb * N + (t >> 1)) * CQK + (size_t)(t & 1) * 8;
    const u8* gv_p = g_v + ((size_t)bb * C + (t >> 3)) * N + (size_t)(t & 7) * 16;
    const u32 qsto = sbase + SM_Q + (u32)((t >> 1) * QKS + (t & 1) * 16);
    const u32 vsto = sbase + SM_V + (u32)((t >> 3) * VS + (t & 7) * 16);

    auto load_q = [&](u32 qWo) {
        asm volatile("cp.async.ca.shared.global [%0],[%1],16;"
                     :: "r"(qsto + qWo), "l"(gq_p) : "memory");
        gq_p += NT * CQK;
    };
    auto load_v = [&](u32 vWo) {
        #pragma unroll
        for (int i8 = 0; i8 < 8; i8++)
            asm volatile("cp.async.cg.shared.global [%0],[%1],16;"
                         :: "r"(vsto + vWo + i8 * (32 * VS)),
                            "l"(gv_p + (size_t)i8 * 32 * N) : "memory");
        gv_p += NT;
    };

    // prologue: Q(0), V(0), Q(1)
    load_q(0);
    load_v(0);
    load_q(QBUF);
    CP_COMMIT();
    CP_WAIT0();
    __syncthreads();

    u32 aK[4];
    ldsm4(aK, sbase + SM_K + (u32)((mt * 16 + ldA) * QKS + ldAc));

    float Lacc0 = 0.f, Lacc8 = 0.f;

    auto s_compute = [&](u32 qRo, u32 pWo) {
        u32 b0[2][4], b1[2][4];
        ldsm4(b0[0], qfragA + qRo);
        ldsm4(b1[0], qfragB + qRo);
        ldsm4(b0[1], qfragA + qRo + 32 * QKS);
        ldsm4(b1[1], qfragB + qRo + 32 * QKS);

        u32 Lt0 = 0, Lt8 = 0;
        char* pb0 = psto0 + pWo;
        char* pb1 = psto1 + pWo;
        #pragma unroll
        for (int nh2 = 0; nh2 < 2; nh2++) {
            float d[4][4];
            #pragma unroll
            for (int j = 0; j < 4; j++)
                #pragma unroll
                for (int e = 0; e < 4; e++) d[j][e] = -SBIAS;
            mma_bf16(d[0], aK, b0[nh2]);
            mma_bf16(d[1], aK, b0[nh2] + 2);
            mma_bf16(d[2], aK, b1[nh2]);
            mma_bf16(d[3], aK, b1[nh2] + 2);

            #pragma unroll
            for (int nt = 0; nt < 4; nt++) {
                u32 e0 = ex2h2(hpack(d[nt][0], d[nt][1]));
                u32 e1 = ex2h2(hpack(d[nt][2], d[nt][3]));
                Lt0 = hadd2(Lt0, e0);
                Lt8 = hadd2(Lt8, e1);
                *(u16*)(pb0 + nh2 * 32 + nt * 8) = e4m3h2(e0);
                *(u16*)(pb1 + nh2 * 32 + nt * 8) = e4m3h2(e1);
            }
        }
        Lacc0 += h2sum(Lt0);
        Lacc8 += h2sum(Lt8);
    };

    float d_acc[2][8][4];
    #pragma unroll
    for (int ct = 0; ct < 2; ct++)
        #pragma unroll
        for (int mp = 0; mp < 8; mp++)
            #pragma unroll
            for (int e = 0; e < 4; e++) d_acc[ct][mp][e] = 0.f;

    s_compute(0, 0);
    __syncthreads();

    u32 qRo = QBUF, qIo = 0, qWo = 2 * QBUF;
    u32 vRo = 0, vWo = VBUF;
    u32 pWo = PBUF, pRo = 0;

    for (int tile = 0; tile < NTILES; ++tile) {
        // issue async loads for upcoming tiles (consumed next iteration)
        if (tile + 2 < NTILES) load_q(qWo);
        if (tile + 1 < NTILES) load_v(vWo);
        CP_COMMIT();

        if (tile + 1 < NTILES) s_compute(qRo, pWo);

        // ---- PV: O += V(tile) @ P^T(tile), fp8 ----
        #pragma unroll
        for (int ks = 0; ks < 4; ks++) {
            u32 av[2][4];
            ldsm4(av[0], vfrag[0] + vRo + ks * 32);
            ldsm4(av[1], vfrag[1] + vRo + ks * 32);
            #pragma unroll
            for (int mp = 0; mp < 4; mp++) {
                u32 bf[4];
                ldsm4(bf, pfrag[mp] + pRo + ks * 32);
                mma_e4m3(d_acc[0][2 * mp    ], av[0], bf);
                mma_e4m3(d_acc[0][2 * mp + 1], av[0], bf + 2);
                mma_e4m3(d_acc[1][2 * mp    ], av[1], bf);
                mma_e4m3(d_acc[1][2 * mp + 1], av[1], bf + 2);
            }
        }

        CP_WAIT0();        // async group (issued at top) must land before reuse
        __syncthreads();

        u32 tq = qRo; qRo = qWo; qWo = qIo; qIo = tq;
        vRo ^= VBUF; vWo ^= VBUF;
        pWo ^= PBUF; pRo ^= PBUF;
    }

    // ---- L reduction (once) ----
    Lacc0 += __shfl_xor_sync(0xffffffffu, Lacc0, 1);
    Lacc0 += __shfl_xor_sync(0xffffffffu, Lacc0, 2);
    Lacc8 += __shfl_xor_sync(0xffffffffu, Lacc8, 1);
    Lacc8 += __shfl_xor_sync(0xffffffffu, Lacc8, 2);
    if (cq == 0) {
        atomicAdd(&L_s[mt * 16 + r],     Lacc0);
        atomicAdd(&L_s[mt * 16 + r + 8], Lacc8);
    }
    __syncthreads();
    if (t < MT) L_s[t] = 1.0f / fmaxf(L_s[t], 1e-30f);
    __syncthreads();

    // ---- epilogue: out = x + gamma * O / L ----
    const float g = gamma[0];
    #pragma unroll
    for (int ct = 0; ct < 2; ct++) {
        #pragma unroll
        for (int half = 0; half < 2; half++) {
            int c = ct0 + ct * 16 + r + half * 8;
            #pragma unroll
            for (int mp = 0; mp < 8; mp++) {
                int mloc = mp * 8 + cq * 2;
                float iL0 = L_s[mloc], iL1 = L_s[mloc + 1];
                size_t idx = ((size_t)bb * C + c) * N + m0 + mloc;
                float2 xv = *(const float2*)&x[idx];
                float2 ov;
                ov.x = xv.x + g * d_acc[ct][mp][half * 2    ] * iL0;
                ov.y = xv.y + g * d_acc[ct][mp][half * 2 + 1] * iL1;
                *(float2*)&out[idx] = ov;
            }
        }
    }
}

// ---------------------------------------------------------------------------
extern "C" void kernel_launch(void* const* d_in, const int* in_sizes, int n_in,
                              void* d_out, int out_size)
{
    const float* x     = (const float*)d_in[0];
    const float* Wq    = (const float*)d_in[1];
    const float* bq    = (const float*)d_in[2];
    const float* Wk    = (const float*)d_in[3];
    const float* bk    = (const float*)d_in[4];
    const float* Wv    = (const float*)d_in[5];
    const float* bv    = (const float*)d_in[6];
    const float* gamma = (const float*)d_in[7];
    float* out = (float*)d_out;

    wcvt_kernel<<<288, 256>>>(Wq, Wk, Wv);

    cudaFuncSetAttribute(proj_mma_kernel,
                         cudaFuncAttributeMaxDynamicSharedMemorySize, PM_TOTAL);
    proj_mma_kernel<<<dim3(N / 64, B), 256, PM_TOTAL>>>(x, bq, bk, bv);

    cudaFuncSetAttribute(attn_kernel,
                         cudaFuncAttributeMaxDynamicSharedMemorySize, SM_TOTAL);
    attn_kernel<<<dim3(N / MT, B), 256, SM_TOTAL>>>(x, gamma, out);
}